// round 4
// baseline (speedup 1.0000x reference)
#include <cuda_runtime.h>
#include <cuda_bf16.h>
#include <cstdint>

// ============================================================================
// ProxyISA loss — bf16x3 split GEMM (fp32-accurate cos) + fused epilogue.
// cos = inputs @ l2norm(proxies)^T, [1024 x 16384], E=512, then per-class
// reductions -> scalar. Split: x = hi + lo (bf16 each);
// cos ~= Ahi*Bhi + Ahi*Blo + Alo*Bhi  (fp32 accum, residual ~2^-18).
// ============================================================================

#define ALPHA 32.0f
#define MRG   0.1f
#define KCON  1.0f
#define LAM   0.1f

#define Bsz 1024
#define Esz 512
#define Csz 16384

#define CPB    128            // classes per CTA
#define NBLK   (Csz / CPB)    // 128 CTAs -> exactly 1 wave
#define TILE_M 128
#define NTIL   (Bsz / TILE_M) // 8
#define KCH    64             // K chunk (elems)
#define NCH    (Esz / KCH)    // 8

#define A_STR  72             // 64 + 8 pad  (144B rows, 16B aligned)
#define BH_STR 520            // 512 + 8 pad (1040B rows)

// ---- device scratch (static; no runtime allocation allowed) ----
__device__ __nv_bfloat16 g_Ah[Bsz * Esz];    // 1 MB
__device__ __nv_bfloat16 g_Al[Bsz * Esz];    // 1 MB
__device__ __nv_bfloat16 g_Bh[Csz * Esz];    // 16 MB
__device__ __nv_bfloat16 g_Bl[Csz * Esz];    // 16 MB
__device__ float2        g_cls[Csz];         // (outlierSim, 1/max(1,eff))
__device__ int           g_cnt[Csz];
__device__ float4        g_part[NBLK];

// ---- smem byte offsets ----
#define OFF_BH   0
#define SZ_BH    (128 * BH_STR * 2)                  // 133120
#define OFF_AH   (OFF_BH + SZ_BH)
#define SZ_A     (128 * A_STR * 2)                   // 18432
#define OFF_AL   (OFF_AH + SZ_A)
#define OFF_BL   (OFF_AL + SZ_A)
#define OFF_F    (OFF_BL + SZ_A)
// floats: outS[128] invE[128] accW[4*128*3] accP[128*3] red[128*4] + tgts[128]
#define SMEM_MAIN (OFF_F + (128 + 128 + 4*128*3 + 128*3 + 128*4) * 4 + 512 + 256)

// ---------------------------------------------------------------------------
__device__ __forceinline__ uint32_t smem_u32(const void* p) {
    uint32_t a;
    asm("{ .reg .u64 t; cvta.to.shared.u64 t, %1; cvt.u32.u64 %0, t; }"
        : "=r"(a) : "l"(p));
    return a;
}
__device__ __forceinline__ void ldmA4(uint32_t* a, uint32_t addr) {
    asm volatile("ldmatrix.sync.aligned.m8n8.x4.shared.b16 {%0,%1,%2,%3}, [%4];"
                 : "=r"(a[0]), "=r"(a[1]), "=r"(a[2]), "=r"(a[3]) : "r"(addr));
}
__device__ __forceinline__ void ldmB2(uint32_t& b0, uint32_t& b1, uint32_t addr) {
    asm volatile("ldmatrix.sync.aligned.m8n8.x2.shared.b16 {%0,%1}, [%2];"
                 : "=r"(b0), "=r"(b1) : "r"(addr));
}
__device__ __forceinline__ void mma16816(float* d, const uint32_t* a,
                                         uint32_t b0, uint32_t b1) {
    asm volatile(
        "mma.sync.aligned.m16n8k16.row.col.f32.bf16.bf16.f32 "
        "{%0,%1,%2,%3}, {%4,%5,%6,%7}, {%8,%9}, {%0,%1,%2,%3};"
        : "+f"(d[0]), "+f"(d[1]), "+f"(d[2]), "+f"(d[3])
        : "r"(a[0]), "r"(a[1]), "r"(a[2]), "r"(a[3]), "r"(b0), "r"(b1));
}
__device__ __forceinline__ void split2(float x, __nv_bfloat16& h, __nv_bfloat16& l) {
    h = __float2bfloat16_rn(x);
    l = __float2bfloat16_rn(x - __bfloat162float(h));
}

// ---------------------------------------------------------------------------
__global__ void prep_inputs_kernel(const float* __restrict__ in) {
    int i = blockIdx.x * blockDim.x + threadIdx.x;           // 65536 threads
    const float4* in4 = (const float4*)in;
    for (int k = i; k < (Bsz * Esz) / 4; k += 65536) {
        float4 v = in4[k];
        __nv_bfloat16 h0, l0, h1, l1, h2, l2, h3, l3;
        split2(v.x, h0, l0); split2(v.y, h1, l1);
        split2(v.z, h2, l2); split2(v.w, h3, l3);
        ((__nv_bfloat162*)g_Ah)[k * 2 + 0] = __nv_bfloat162(h0, h1);
        ((__nv_bfloat162*)g_Ah)[k * 2 + 1] = __nv_bfloat162(h2, h3);
        ((__nv_bfloat162*)g_Al)[k * 2 + 0] = __nv_bfloat162(l0, l1);
        ((__nv_bfloat162*)g_Al)[k * 2 + 1] = __nv_bfloat162(l2, l3);
    }
}

__global__ void prep_proxies_kernel(const float* __restrict__ proxies,
                                    const float* __restrict__ eff,
                                    const float* __restrict__ ls) {
    __shared__ float ws[4];
    int row = blockIdx.x;
    int tid = threadIdx.x;                                    // 128 threads
    float4 v = ((const float4*)proxies)[(size_t)row * 128 + tid];
    float s = v.x * v.x + v.y * v.y + v.z * v.z + v.w * v.w;
    #pragma unroll
    for (int d = 16; d > 0; d >>= 1) s += __shfl_xor_sync(0xffffffffu, s, d);
    if ((tid & 31) == 0) ws[tid >> 5] = s;
    __syncthreads();
    float rn = rsqrtf(ws[0] + ws[1] + ws[2] + ws[3] + 1e-12f);
    size_t base = (size_t)row * 256 + tid * 2;
    __nv_bfloat16 h0, l0, h1, l1, h2, l2, h3, l3;
    split2(v.x * rn, h0, l0); split2(v.y * rn, h1, l1);
    split2(v.z * rn, h2, l2); split2(v.w * rn, h3, l3);
    ((__nv_bfloat162*)g_Bh)[base + 0] = __nv_bfloat162(h0, h1);
    ((__nv_bfloat162*)g_Bh)[base + 1] = __nv_bfloat162(h2, h3);
    ((__nv_bfloat162*)g_Bl)[base + 0] = __nv_bfloat162(l0, l1);
    ((__nv_bfloat162*)g_Bl)[base + 1] = __nv_bfloat162(l2, l3);
    if (tid == 0) {
        float e = eff[row], l = ls[row];
        float wb = 1.0f / (1.0f + log1pf(e));
        float eta = (1.0f + KCON * (1.0f - l)) * wb + LAM;
        g_cls[row] = make_float2(l - eta, 1.0f / fmaxf(1.0f, e));
        g_cnt[row] = 0;
    }
}

__global__ void prep_count_kernel(const int* __restrict__ targets) {
    int i = blockIdx.x * blockDim.x + threadIdx.x;
    if (i < Bsz) atomicAdd(&g_cnt[targets[i]], 1);
}

// ---------------------------------------------------------------------------
__global__ void __launch_bounds__(256, 1)
main_kernel(const int* __restrict__ targets) {
    extern __shared__ char smem[];
    __nv_bfloat16* Bh = (__nv_bfloat16*)(smem + OFF_BH);      // [128][520]
    __nv_bfloat16* Ah = (__nv_bfloat16*)(smem + OFF_AH);      // [128][72]
    __nv_bfloat16* Al = (__nv_bfloat16*)(smem + OFF_AL);      // [128][72]
    __nv_bfloat16* Bl = (__nv_bfloat16*)(smem + OFF_BL);      // [128][72]
    float* outS = (float*)(smem + OFF_F);
    float* invE = outS + 128;
    float* accW = invE + 128;            // [4][128][3]
    float* accP = accW + 4 * 128 * 3;    // [128][3]
    float* red  = accP + 128 * 3;        // [128][4]
    int*   tgts = (int*)(red + 128 * 4); // [128]

    const int tid  = threadIdx.x;
    const int lane = tid & 31;
    const int w    = tid >> 5;           // 8 warps
    const int mw   = w >> 1;             // 0..3 (M 32-row group)
    const int nwId = w & 1;              // 0..1 (N 64-col half)
    const int cb   = blockIdx.x;

    const uint32_t sbase   = smem_u32(smem);
    const uint32_t bh_base = sbase + OFF_BH;
    const uint32_t ah_base = sbase + OFF_AH;
    const uint32_t al_base = sbase + OFF_AL;
    const uint32_t bl_base = sbase + OFF_BL;

    // ---- resident B_hi slice (128 classes x 512 bf16) ----
    for (int i = tid; i < 128 * 64; i += 256) {
        int r = i >> 6, s = i & 63;
        uint4 v = *(const uint4*)&g_Bh[(size_t)(cb * 128 + r) * Esz + s * 8];
        *(uint4*)&Bh[r * BH_STR + s * 8] = v;
    }
    if (tid < 128) {
        float2 p = g_cls[cb * 128 + tid];
        outS[tid] = p.x;
        invE[tid] = p.y;
        accP[tid * 3 + 0] = 0.0f;
        accP[tid * 3 + 1] = 0.0f;
        accP[tid * 3 + 2] = 0.0f;
    }
    __syncthreads();

    for (int tile = 0; tile < NTIL; ++tile) {
        if (tid < 128) tgts[tid] = targets[tile * 128 + tid];

        float acc[2][8][4];
        #pragma unroll
        for (int mf = 0; mf < 2; mf++)
            #pragma unroll
            for (int nf = 0; nf < 8; nf++)
                #pragma unroll
                for (int q = 0; q < 4; q++) acc[mf][nf][q] = 0.0f;

        for (int ch = 0; ch < NCH; ++ch) {
            __syncthreads();   // protect As/Bl reuse + tgts visibility
            for (int i = tid; i < 128 * 8; i += 256) {
                int r = i >> 3, s = i & 7;
                size_t ga = (size_t)(tile * 128 + r) * Esz + ch * KCH + s * 8;
                *(uint4*)&Ah[r * A_STR + s * 8] = *(const uint4*)&g_Ah[ga];
                *(uint4*)&Al[r * A_STR + s * 8] = *(const uint4*)&g_Al[ga];
                size_t gb = (size_t)(cb * 128 + r) * Esz + ch * KCH + s * 8;
                *(uint4*)&Bl[r * A_STR + s * 8] = *(const uint4*)&g_Bl[gb];
            }
            __syncthreads();

            #pragma unroll
            for (int ks = 0; ks < KCH / 16; ++ks) {
                const int kb = ks * 16;
                uint32_t ah[2][4], al[2][4];
                {
                    int sub = lane >> 3, r = lane & 7;
                    int rofs = ((sub & 1) ? 8 : 0) + r;
                    int cofs = kb + ((sub >> 1) ? 8 : 0);
                    #pragma unroll
                    for (int mf = 0; mf < 2; mf++) {
                        int row = mw * 32 + mf * 16 + rofs;
                        ldmA4(ah[mf], ah_base + (row * A_STR + cofs) * 2);
                        ldmA4(al[mf], al_base + (row * A_STR + cofs) * 2);
                    }
                }
                int subb = (lane >> 3) & 1, rb = lane & 7;
                #pragma unroll
                for (int nf = 0; nf < 8; nf++) {
                    int row = nwId * 64 + nf * 8 + rb;
                    uint32_t bh0, bh1, bl0, bl1;
                    ldmB2(bh0, bh1,
                          bh_base + (row * BH_STR + ch * KCH + kb + subb * 8) * 2);
                    ldmB2(bl0, bl1,
                          bl_base + (row * A_STR + kb + subb * 8) * 2);
                    #pragma unroll
                    for (int mf = 0; mf < 2; mf++) {
                        mma16816(acc[mf][nf], ah[mf], bh0, bh1);
                        mma16816(acc[mf][nf], ah[mf], bl0, bl1);
                        mma16816(acc[mf][nf], al[mf], bh0, bh1);
                    }
                }
            }
        }

        // ---- epilogue: per-column sums (sP, sN, sM) ----
        #pragma unroll
        for (int nf = 0; nf < 8; nf++) {
            int cl0 = nwId * 64 + nf * 8 + 2 * (lane & 3);
            float o0 = outS[cl0], o1 = outS[cl0 + 1];
            float e0 = invE[cl0], e1 = invE[cl0 + 1];
            int gc0 = cb * 128 + cl0, gc1 = gc0 + 1;
            float sP0 = 0, sN0 = 0, sM0 = 0, sP1 = 0, sN1 = 0, sM1 = 0;
            #pragma unroll
            for (int mf = 0; mf < 2; mf++) {
                #pragma unroll
                for (int h = 0; h < 2; h++) {
                    int row = mw * 32 + (lane >> 2) + h * 8 + mf * 16;
                    int tg = tgts[row];
                    float c0v = acc[mf][nf][h * 2 + 0];
                    float c1v = acc[mf][nf][h * 2 + 1];
                    if (tg == gc0) {
                        sP0 += __expf(ALPHA * (MRG - c0v));
                    } else {
                        float m = (c0v < o0) ? e0 : 1.0f;
                        sN0 += __expf(ALPHA * (c0v + MRG) * m);
                        sM0 += m;
                    }
                    if (tg == gc1) {
                        sP1 += __expf(ALPHA * (MRG - c1v));
                    } else {
                        float m = (c1v < o1) ? e1 : 1.0f;
                        sN1 += __expf(ALPHA * (c1v + MRG) * m);
                        sM1 += m;
                    }
                }
            }
            #pragma unroll
            for (int d = 4; d < 32; d <<= 1) {
                sP0 += __shfl_xor_sync(0xffffffffu, sP0, d);
                sN0 += __shfl_xor_sync(0xffffffffu, sN0, d);
                sM0 += __shfl_xor_sync(0xffffffffu, sM0, d);
                sP1 += __shfl_xor_sync(0xffffffffu, sP1, d);
                sN1 += __shfl_xor_sync(0xffffffffu, sN1, d);
                sM1 += __shfl_xor_sync(0xffffffffu, sM1, d);
            }
            if (lane < 4) {
                int c = nwId * 64 + nf * 8 + 2 * lane;
                float* wp = &accW[(mw * 128 + c) * 3];
                wp[0] = sP0; wp[1] = sN0; wp[2] = sM0;
                wp[3] = sP1; wp[4] = sN1; wp[5] = sM1;
            }
        }
        __syncthreads();
        if (tid < 128) {   // fixed-order row-group reduce -> persistent acc
            float s0 = 0, s1 = 0, s2 = 0;
            #pragma unroll
            for (int g = 0; g < 4; g++) {
                const float* wp = &accW[(g * 128 + tid) * 3];
                s0 += wp[0]; s1 += wp[1]; s2 += wp[2];
            }
            accP[tid * 3 + 0] += s0;
            accP[tid * 3 + 1] += s1;
            accP[tid * 3 + 2] += s2;
        }
        __syncthreads();
    }

    // ---- per-class finalize + CTA partial ----
    if (tid < 128) {
        float sP = accP[tid * 3 + 0];
        float sN = accP[tid * 3 + 1];
        float sM = accP[tid * 3 + 2];
        int cnt = g_cnt[cb * 128 + tid];
        int Ncnt = Bsz - cnt;
        red[tid * 4 + 0] = log1pf(sP);
        red[tid * 4 + 1] = log1pf(sN);
        red[tid * 4 + 2] = (Ncnt > 0) ? sM / (float)Ncnt : 0.0f;
        red[tid * 4 + 3] = (cnt > 0) ? 1.0f : 0.0f;
    }
    __syncthreads();
    if (tid == 0) {
        float a = 0, b = 0, c = 0, d = 0;
        for (int i = 0; i < 128; i++) {
            a += red[i * 4 + 0];
            b += red[i * 4 + 1];
            c += red[i * 4 + 2];
            d += red[i * 4 + 3];
        }
        g_part[cb] = make_float4(a, b, c, d);
    }
}

__global__ void finalize_kernel(float* __restrict__ out) {
    if (threadIdx.x == 0) {
        float p = 0, n = 0, nw = 0, pw = 0;
        for (int i = 0; i < NBLK; i++) {
            float4 v = g_part[i];
            p += v.x; n += v.y; nw += v.z; pw += v.w;
        }
        out[0] = p / pw + n / nw;
    }
}

// ---------------------------------------------------------------------------
extern "C" void kernel_launch(void* const* d_in, const int* in_sizes, int n_in,
                              void* d_out, int out_size) {
    const float* inputs  = (const float*)d_in[0];
    const int*   targets = (const int*)d_in[1];
    const float* proxies = (const float*)d_in[2];
    const float* eff     = (const float*)d_in[3];
    const float* ls      = (const float*)d_in[4];
    float* out = (float*)d_out;

    cudaFuncSetAttribute(main_kernel,
                         cudaFuncAttributeMaxDynamicSharedMemorySize, SMEM_MAIN);

    prep_inputs_kernel<<<256, 256>>>(inputs);
    prep_proxies_kernel<<<Csz, 128>>>(proxies, eff, ls);
    prep_count_kernel<<<4, 256>>>(targets);
    main_kernel<<<NBLK, 256, SMEM_MAIN>>>(targets);
    finalize_kernel<<<1, 32>>>(out);
}